// round 16
// baseline (speedup 1.0000x reference)
#include <cuda_runtime.h>
#include <math_constants.h>
#include <stdint.h>

// PQHead: out[b, m*6+d] = codebooks[m, argmax_k <x[b,m*6:...], cb[m,k,:]>, d]
// (forward value of the straight-through estimator == discrete codeword)
//
// FROZEN NUMERICS: dot = x0*c0 then fma.rn chain d=1..5 (scalar FFMA), argmax
// exact, FIRST-max tie rule. ~2 argmax flips total breach 1e-3 -> any
// reassociation / reduced precision is mathematically excluded.
//
// LESSONS: R3/R4 spills; R7 f32x2 half-rate; R12 cp.async; R13 LDS width law
// (cb smem cost = 6/RPT wf/pair, layout-invariant). RPT=2+prefetch: L1 84%
// wall. RPT=4 no-prefetch: tile-head DRAM stalls (issue 62%). FFMA rt=1 on
// GB300 -> arithmetic floor ~26us; structure is the binding constraint.
// R16: RPT=4 + hybrid prefetch (rows 0-1 in registers, rows 2-3 via real
// discarded LDG touches that guarantee L1 residency) inside the 64-reg cap.

#define B_ROWS   32768
#define M_SUB    128
#define QM       16                      // m's per block (1/8 split)
#define NGRP     (M_SUB / QM)            // 8
#define K_CODES  32
#define D_SUB    6
#define DIM      768
#define RPT      4                       // rows per thread
#define TPB      256                     // 16 row-groups x 16 m
#define TILE_ROWS (RPT * (TPB / QM))     // 64
#define NTILES   (B_ROWS / TILE_ROWS)    // 512 per group
#define BLK_PER_G 74                     // 8 groups x 74 = 592 = 4/SM
#define NBLOCKS  (NGRP * BLK_PER_G)

__device__ __forceinline__ void l1_touch(const float* p) {
    // Real load, result discarded: guaranteed L1 fill (prefetch may be dropped).
    float v;
    asm volatile("ld.global.nc.f32 %0, [%1];" : "=f"(v) : "l"(p));
    asm volatile("" :: "f"(v));
}

__global__ void __launch_bounds__(TPB, 4)
pq_head_kernel(const float* __restrict__ x,
               const float* __restrict__ cb,
               float* __restrict__ out)
{
    // Codebook split: cbA[k*16+m] = (d0,d1,d2,d3), cbB[k*16+m] = (d4,d5).
    __shared__ float4 cbA[K_CODES * QM];     // 8KB
    __shared__ float2 cbB[K_CODES * QM];     // 4KB

    const int t = threadIdx.x;
    const int grp = blockIdx.x / BLK_PER_G;      // which m-group this block owns
    const int bstart = blockIdx.x % BLK_PER_G;

    // One-time codebook load for this group.
    {
        const float* cbg = cb + (size_t)grp * QM * (K_CODES * D_SUB);
        for (int i = t; i < QM * K_CODES; i += TPB) {
            int mloc = i / K_CODES;
            int k    = i - mloc * K_CODES;
            const float* src = cbg + (size_t)mloc * (K_CODES * D_SUB) + k * D_SUB;
            cbA[k * QM + mloc] = make_float4(src[0], src[1], src[2], src[3]);
            cbB[k * QM + mloc] = make_float2(src[4], src[5]);
        }
    }
    __syncthreads();

    const int mloc = t & (QM - 1);
    const int g    = t >> 4;             // row-group 0..15
    const int col0 = (grp * QM + mloc) * D_SUB;

    const size_t step = (size_t)BLK_PER_G * TILE_ROWS * DIM;
    const float* xp = x   + (size_t)(bstart * TILE_ROWS + g * RPT) * DIM + col0;
    float*       op = out + (size_t)(bstart * TILE_ROWS + g * RPT) * DIM + col0;

    // Prologue: register-load rows 0-1 of the first tile.
    float xv[RPT][D_SUB];
    #pragma unroll
    for (int r = 0; r < 2; r++) {
        const float2* p = reinterpret_cast<const float2*>(xp + (size_t)r * DIM);
        float2 a = p[0], bq = p[1], c = p[2];
        xv[r][0] = a.x;  xv[r][1] = a.y;
        xv[r][2] = bq.x; xv[r][3] = bq.y;
        xv[r][4] = c.x;  xv[r][5] = c.y;
    }

    for (int tile = bstart; tile < NTILES; tile += BLK_PER_G) {
        // ---- Head: load rows 2-3 (L1-resident: touched one iteration ago).
        #pragma unroll
        for (int r = 2; r < RPT; r++) {
            const float2* p = reinterpret_cast<const float2*>(xp + (size_t)r * DIM);
            float2 a = p[0], bq = p[1], c = p[2];
            xv[r][0] = a.x;  xv[r][1] = a.y;
            xv[r][2] = bq.x; xv[r][3] = bq.y;
            xv[r][4] = c.x;  xv[r][5] = c.y;
        }

        const float* nxp = (tile + BLK_PER_G < NTILES) ? (xp + step) : xp;

        // ---- Register prefetch of next tile's rows 0-1.
        float nx[2][D_SUB];
        #pragma unroll
        for (int r = 0; r < 2; r++) {
            const float2* p = reinterpret_cast<const float2*>(nxp + (size_t)r * DIM);
            float2 a = p[0], bq = p[1], c = p[2];
            nx[r][0] = a.x;  nx[r][1] = a.y;
            nx[r][2] = bq.x; nx[r][3] = bq.y;
            nx[r][4] = c.x;  nx[r][5] = c.y;
        }
        // ---- L1-fill touches for next tile's rows 2-3 (both possible lines).
        #pragma unroll
        for (int r = 2; r < RPT; r++) {
            l1_touch(nxp + (size_t)r * DIM);
            l1_touch(nxp + (size_t)r * DIM + 5);
        }

        // ---- k = 0 peeled: best = dot, idx = 0.
        float best[RPT];
        int   idx[RPT];
        {
            const float4 ca  = cbA[mloc];
            const float2 cbv = cbB[mloc];
            #pragma unroll
            for (int r = 0; r < RPT; r++) {
                float dot = xv[r][0] * ca.x;
                dot = fmaf(xv[r][1], ca.y, dot);
                dot = fmaf(xv[r][2], ca.z, dot);
                dot = fmaf(xv[r][3], ca.w, dot);
                dot = fmaf(xv[r][4], cbv.x, dot);
                dot = fmaf(xv[r][5], cbv.y, dot);
                best[r] = dot;
                idx[r]  = 0;
            }
        }

        // ---- k = 1..31; unroll 2 bounds cb hoisting under the 64-reg cap.
        #pragma unroll 2
        for (int k = 1; k < K_CODES; k++) {
            const float4 ca  = cbA[k * QM + mloc];
            const float2 cbv = cbB[k * QM + mloc];
            #pragma unroll
            for (int r = 0; r < RPT; r++) {
                float dot = xv[r][0] * ca.x;
                dot = fmaf(xv[r][1], ca.y, dot);
                dot = fmaf(xv[r][2], ca.z, dot);
                dot = fmaf(xv[r][3], ca.w, dot);
                dot = fmaf(xv[r][4], cbv.x, dot);
                dot = fmaf(xv[r][5], cbv.y, dot);
                // EXACT argmax, FIRST-max tie rule; FMNMX value chain keeps
                // the 13-cyc predicate latency off the loop-carried path.
                bool p  = dot > best[r];
                best[r] = fmaxf(best[r], dot);
                idx[r]  = p ? k : idx[r];
            }
        }

        // ---- Emit the winning codeword rows.
        #pragma unroll
        for (int r = 0; r < RPT; r++) {
            const float4 oa = cbA[idx[r] * QM + mloc];
            const float2 ob = cbB[idx[r] * QM + mloc];
            float2* po = reinterpret_cast<float2*>(op + (size_t)r * DIM);
            po[0] = make_float2(oa.x, oa.y);
            po[1] = make_float2(oa.z, oa.w);
            po[2] = ob;
        }

        // ---- Rotate prefetched rows 0-1 in.
        #pragma unroll
        for (int r = 0; r < 2; r++)
            #pragma unroll
            for (int d = 0; d < D_SUB; d++)
                xv[r][d] = nx[r][d];

        xp = nxp;
        op += step;
    }
}

extern "C" void kernel_launch(void* const* d_in, const int* in_sizes, int n_in,
                              void* d_out, int out_size)
{
    const float* x  = (const float*)d_in[0];
    const float* cb = (const float*)d_in[1];
    float* out      = (float*)d_out;

    pq_head_kernel<<<NBLOCKS, TPB>>>(x, cb, out);
}